// round 6
// baseline (speedup 1.0000x reference)
#include <cuda_runtime.h>
#include <cuda_bf16.h>

#define TT 512
#define LL 62
#define KK 64
#define GG 8
#define NTH 128

__global__ void init_out_kernel(float* out) { out[0] = 0.0f; }

__device__ __forceinline__ __nv_bfloat162 u32_as_bf2(unsigned int v) {
    __nv_bfloat162 r;
    *reinterpret_cast<unsigned int*>(&r) = v;
    return r;
}
__device__ __forceinline__ unsigned int bf2_as_u32(__nv_bfloat162 v) {
    return *reinterpret_cast<unsigned int*>(&v);
}

// Half-dot: sum over this thread's 32 states (offset h*32) of u[k]*E[k][col].
// Returns bf162 with (even-k, odd-k) partial lane sums.
__device__ __forceinline__ __nv_bfloat162 dot32h(const __nv_bfloat16* __restrict__ ubuf,
                                                 int h,
                                                 const __nv_bfloat162* __restrict__ Epk) {
    const uint4* up = reinterpret_cast<const uint4*>(ubuf + h * 32);
    __nv_bfloat162 z; *reinterpret_cast<unsigned int*>(&z) = 0u;
    __nv_bfloat162 a0 = z, a1 = z, a2 = z, a3 = z;
    #pragma unroll
    for (int q = 0; q < 4; ++q) {
        uint4 v = up[q];
        a0 = __hfma2(u32_as_bf2(v.x), Epk[4 * q + 0], a0);
        a1 = __hfma2(u32_as_bf2(v.y), Epk[4 * q + 1], a1);
        a2 = __hfma2(u32_as_bf2(v.z), Epk[4 * q + 2], a2);
        a3 = __hfma2(u32_as_bf2(v.w), Epk[4 * q + 3], a3);
    }
    return __hadd2(__hadd2(a0, a1), __hadd2(a2, a3));
}

// Combine: exchange with partner lane (xor 1), add, lane-sum in fp32.
__device__ __forceinline__ float combine(__nv_bfloat162 part) {
    unsigned int o = __shfl_xor_sync(0xffffffffu, bf2_as_u32(part), 1);
    __nv_bfloat162 s = __hadd2(part, u32_as_bf2(o));
    float2 f = __bfloat1622float2(s);
    return f.x + f.y;
}

__global__ __launch_bounds__(NTH) void crf_forward_kernel(
    const float* __restrict__ pred,      // [B, T, L]
    const int*   __restrict__ ref,       // [B, T]
    const int*   __restrict__ seq_len,   // [B]
    const float* __restrict__ trans,     // [K, K]
    float* __restrict__ out)             // scalar
{
    const int b    = blockIdx.x;
    const int tid  = threadIdx.x;
    const int col  = tid >> 1;           // 0..63, two threads per column
    const int h    = tid & 1;            // state-half owned by this thread
    const int lane = tid & 31;
    const int wid  = tid >> 5;

    __shared__ __align__(16) __nv_bfloat16 u_sh[2][KK];
    __shared__ float red[4];
    __shared__ float red2[4];

    const float* predb = pred + (size_t)b * TT * LL;
    const int*   refb  = ref  + (size_t)b * TT;
    const int    sl    = seq_len[b];

    // E sub-column: states 32h..32h+31 of column `col`, bf16x2 pairs.
    // Rows 62,63 are exp(-10000) = 0 exactly.
    __nv_bfloat162 Epk[16];
    #pragma unroll
    for (int p = 0; p < 16; ++p) {
        float e0 = __expf(trans[(32 * h + 2 * p + 0) * KK + col]);
        float e1 = __expf(trans[(32 * h + 2 * p + 1) * KK + col]);
        Epk[p] = __floats2bfloat162_rn(e0, e1);
    }

    // invariant: u_sh = exp(alpha - c); init labels 1 at c=-1000, start/end 0
    // (start's outgoing E row is 0 so its unit mass never propagates).
    float c = -1000.0f;
    if (h == 0) u_sh[0][col] = __float2bfloat16((col < LL) ? 1.0f : 0.0f);
    int cur = 0;

    // eobs register pipeline, one 8-step group ahead
    const bool is_lab = (col < LL);
    float eobsA[GG], eobsB[GG];
    #pragma unroll
    for (int i = 0; i < GG; ++i)
        eobsA[i] = is_lab ? __expf(__ldg(&predb[i * LL + col])) : 0.0f;

    int s = 1;
    while (s + GG <= sl + 1) {               // steps s..s+7, all emission steps
        #pragma unroll
        for (int i = 0; i < GG; ++i) {       // prefetch steps s+8..s+15
            const int row = s + GG - 1 + i;
            eobsB[i] = (is_lab && row < TT) ? __expf(__ldg(&predb[row * LL + col]))
                                            : 0.0f;
        }
        #pragma unroll
        for (int i = 0; i < GG; ++i) {
            __syncthreads();
            // deferred renorm: scale whole vector by 1/u0 at steps i=0 (not
            // the very first) and i=4; computed in parallel with the dot.
            float scale = eobsA[i];
            const bool rn = ((i & 3) == 0) && !(i == 0 && s == 1);
            float u0 = 1.0f;
            if (rn) {
                u0 = __bfloat162float(u_sh[cur][0]);
                scale *= __frcp_rn(u0);
            }
            const float dotv = combine(dot32h(u_sh[cur], h, Epk));
            if (rn) c += __logf(u0);
            const float un = scale * dotv;
            if (h == 0) u_sh[cur ^ 1][col] = __float2bfloat16(un);
            cur ^= 1;
        }
        #pragma unroll
        for (int i = 0; i < GG; ++i) eobsA[i] = eobsB[i];
        s += GG;
    }

    const int rem = sl + 1 - s;              // 0..7 remaining emission steps
    #pragma unroll
    for (int i = 0; i < GG - 1; ++i) {
        if (i >= rem) break;
        __syncthreads();
        float scale = eobsA[i];
        const bool rn = ((i & 3) == 0) && !(i == 0 && s == 1);
        float u0 = 1.0f;
        if (rn) {
            u0 = __bfloat162float(u_sh[cur][0]);
            scale *= __frcp_rn(u0);
        }
        const float dotv = combine(dot32h(u_sh[cur], h, Epk));
        if (rn) c += __logf(u0);
        const float un = scale * dotv;
        if (h == 0) u_sh[cur ^ 1][col] = __float2bfloat16(un);
        cur ^= 1;
    }
    __syncthreads();

    // ---- boundary step (sl+1) in log domain for all 64 columns ----
    const float dB = combine(dot32h(u_sh[cur], h, Epk));
    float obs_b;
    if (col < LL)
        obs_b = ((sl < TT) ? predb[sl * LL + col] : 0.0f) - 1000.0f;
    else
        obs_b = (col == LL) ? -1000.0f : 0.0f;
    const float alpha_fin = obs_b + c + __logf(dB);

    // ---- all-paths: logsumexp over 64 columns (only h==0 contributes) ----
    float v = (h == 0) ? alpha_fin : -3.0e38f;
    #pragma unroll
    for (int off = 16; off; off >>= 1)
        v = fmaxf(v, __shfl_xor_sync(0xffffffffu, v, off));
    if (lane == 0) red[wid] = v;
    __syncthreads();
    const float M = fmaxf(fmaxf(red[0], red[1]), fmaxf(red[2], red[3]));

    float e = (h == 0) ? __expf(alpha_fin - M) : 0.0f;
    #pragma unroll
    for (int off = 16; off; off >>= 1)
        e += __shfl_xor_sync(0xffffffffu, e, off);
    if (lane == 0) red2[wid] = e;
    __syncthreads();
    const float all_paths = M + __logf((red2[0] + red2[1]) + (red2[2] + red2[3]));

    // ---- gold (real) score, exact fp32, strided over 128 threads ----
    float gold = 0.0f;
    for (int t = tid; t < sl; t += NTH)
        gold += predb[t * LL + refb[t]];
    for (int t = tid; t <= sl; t += NTH) {
        const int from = (t == 0)  ? LL       : refb[t - 1];
        const int to   = (t == sl) ? (LL + 1) : refb[t];
        gold += trans[from * KK + to];
    }
    #pragma unroll
    for (int off = 16; off; off >>= 1)
        gold += __shfl_xor_sync(0xffffffffu, gold, off);
    if (lane == 0) red[wid] = gold;
    __syncthreads();
    const float gold_total = (red[0] + red[1]) + (red[2] + red[3]);

    if (tid == 0)
        atomicAdd(out, all_paths - gold_total);
}

extern "C" void kernel_launch(void* const* d_in, const int* in_sizes, int n_in,
                              void* d_out, int out_size)
{
    const float* pred    = (const float*)d_in[0];
    const int*   ref     = (const int*)d_in[1];
    const int*   seq_len = (const int*)d_in[2];
    const float* trans   = (const float*)d_in[3];
    float*       out     = (float*)d_out;

    const int B = in_sizes[2];   // 1024

    init_out_kernel<<<1, 1>>>(out);
    crf_forward_kernel<<<B, NTH>>>(pred, ref, seq_len, trans, out);
}